// round 4
// baseline (speedup 1.0000x reference)
#include <cuda_runtime.h>

// Problem constants
#define NN   30000
#define EE   480000
#define GG   64
#define INC  24
#define HH   512
#define LL   6

// ---------------------------------------------------------------------------
// Scratch (device globals — no allocations allowed anywhere)
// ---------------------------------------------------------------------------
__device__ float g_h  [(size_t)NN * HH];        // node state
__device__ float g_t1 [(size_t)NN * HH];        // MLP hidden
__device__ float g_msg[(size_t)NN * HH];        // per-node message
__device__ float g_m  [(size_t)NN * HH];        // aggregated message
__device__ float g_gi [(size_t)NN * 3 * HH];    // GRU input gates
__device__ float g_gh [(size_t)NN * 3 * HH];    // GRU hidden gates
__device__ float g_pool[GG * HH];
__device__ float g_cnt [GG];
__device__ int   g_eidx[2 * EE];                // converted edge index (int32)
__device__ int   g_batch[NN];                   // converted batch (int32)
__device__ int   g_flag[2];                     // dtype flags: [0]=edges, [1]=batch

// ---------------------------------------------------------------------------
// dtype detection: int64 buffers (values < 2^31) have all odd 32-bit words == 0
// ---------------------------------------------------------------------------
__global__ void detect_k(const unsigned* __restrict__ p, int pairs, int slot)
{
    __shared__ int any;
    if (threadIdx.x == 0) any = 0;
    __syncthreads();
    int lim = pairs < 8192 ? pairs : 8192;
    for (int i = threadIdx.x; i < lim; i += blockDim.x)
        if (p[2 * i + 1] != 0u) any = 1;
    __syncthreads();
    if (threadIdx.x == 0) g_flag[slot] = (any == 0) ? 1 : 0;
}

__global__ void convert_k(const void* __restrict__ in, int n, int* __restrict__ out, int slot)
{
    int i = blockIdx.x * blockDim.x + threadIdx.x;
    if (i >= n) return;
    if (g_flag[slot])
        out[i] = (int)(((const long long*)in)[i]);
    else
        out[i] = ((const int*)in)[i];
}

// ---------------------------------------------------------------------------
// Generic SGEMM: C[M,Nc] = act(A[M,K] @ W[K,Nc] + bias), optional second store.
// BM=BN=128, BK=8, 256 threads, 8x8 microtile, double-buffered smem.
// Requires: K % 8 == 0, Nc % 128 == 0, 16B-aligned A rows (K % 4 == 0).
// ---------------------------------------------------------------------------
__global__ __launch_bounds__(256, 2)
void sgemm_kernel(const float* __restrict__ A, const float* __restrict__ W,
                  const float* __restrict__ bias, float* __restrict__ C,
                  float* __restrict__ C2, int M, int K, int Nc, int do_relu)
{
    __shared__ float As[2][8][128];
    __shared__ float Bs[2][8][128];

    const int tid = threadIdx.x;
    const int bm = blockIdx.y * 128;
    const int bn = blockIdx.x * 128;

    const int arow = tid >> 1;            // 0..127
    const int acol = (tid & 1) << 2;      // 0 or 4
    const int brow = tid >> 5;            // 0..7
    const int bcol = (tid & 31) << 2;     // 0..124

    const int ty = tid >> 4;              // 0..15
    const int tx = tid & 15;              // 0..15

    float acc[8][8];
#pragma unroll
    for (int i = 0; i < 8; i++)
#pragma unroll
        for (int j = 0; j < 8; j++) acc[i][j] = 0.f;

    const int grow = bm + arow;
    const float* Arow = A + (size_t)grow * K;

    float4 av, bv;
    av = (grow < M) ? *(const float4*)(Arow + acol) : make_float4(0.f, 0.f, 0.f, 0.f);
    bv = *(const float4*)(W + (size_t)brow * Nc + bn + bcol);

    As[0][acol + 0][arow] = av.x;
    As[0][acol + 1][arow] = av.y;
    As[0][acol + 2][arow] = av.z;
    As[0][acol + 3][arow] = av.w;
    *(float4*)&Bs[0][brow][bcol] = bv;
    __syncthreads();

    int buf = 0;
    for (int k0 = 0; k0 < K; k0 += 8) {
        const bool next = (k0 + 8) < K;
        if (next) {
            av = (grow < M) ? *(const float4*)(Arow + k0 + 8 + acol)
                            : make_float4(0.f, 0.f, 0.f, 0.f);
            bv = *(const float4*)(W + (size_t)(k0 + 8 + brow) * Nc + bn + bcol);
        }
#pragma unroll
        for (int kk = 0; kk < 8; kk++) {
            float4 a0 = *(const float4*)&As[buf][kk][ty * 8];
            float4 a1 = *(const float4*)&As[buf][kk][ty * 8 + 4];
            float4 b0 = *(const float4*)&Bs[buf][kk][tx * 8];
            float4 b1 = *(const float4*)&Bs[buf][kk][tx * 8 + 4];
            float a[8] = {a0.x, a0.y, a0.z, a0.w, a1.x, a1.y, a1.z, a1.w};
            float b[8] = {b0.x, b0.y, b0.z, b0.w, b1.x, b1.y, b1.z, b1.w};
#pragma unroll
            for (int i = 0; i < 8; i++)
#pragma unroll
                for (int j = 0; j < 8; j++)
                    acc[i][j] = fmaf(a[i], b[j], acc[i][j]);
        }
        if (next) {
            const int nbuf = buf ^ 1;
            As[nbuf][acol + 0][arow] = av.x;
            As[nbuf][acol + 1][arow] = av.y;
            As[nbuf][acol + 2][arow] = av.z;
            As[nbuf][acol + 3][arow] = av.w;
            *(float4*)&Bs[nbuf][brow][bcol] = bv;
            __syncthreads();
            buf = nbuf;
        }
    }

    float bvals[8];
#pragma unroll
    for (int j = 0; j < 8; j++) bvals[j] = bias[bn + tx * 8 + j];

#pragma unroll
    for (int i = 0; i < 8; i++) {
        int row = bm + ty * 8 + i;
        if (row >= M) continue;
        float o[8];
#pragma unroll
        for (int j = 0; j < 8; j++) {
            float v = acc[i][j] + bvals[j];
            if (do_relu) v = fmaxf(v, 0.f);
            o[j] = v;
        }
        float4* cp = (float4*)(C + (size_t)row * Nc + bn + tx * 8);
        cp[0] = make_float4(o[0], o[1], o[2], o[3]);
        cp[1] = make_float4(o[4], o[5], o[6], o[7]);
        if (C2) {
            float4* cp2 = (float4*)(C2 + (size_t)row * Nc + bn + tx * 8);
            cp2[0] = make_float4(o[0], o[1], o[2], o[3]);
            cp2[1] = make_float4(o[4], o[5], o[6], o[7]);
        }
    }
}

// ---------------------------------------------------------------------------
// Edge scatter: m[dst] += msg[src]   (one warp per edge; m pre-initialized = msg)
// ---------------------------------------------------------------------------
__global__ void scatter_k(const float* __restrict__ msg, float* __restrict__ m)
{
    int gw = (blockIdx.x * blockDim.x + threadIdx.x) >> 5;
    int lane = threadIdx.x & 31;
    if (gw >= EE) return;
    int s = g_eidx[gw];
    int d = g_eidx[EE + gw];
    const float4* ms = (const float4*)(msg + (size_t)s * HH);
    float* md = m + (size_t)d * HH;
#pragma unroll
    for (int i = 0; i < 4; i++) {
        int c = lane + i * 32;                // float4 index 0..127
        float4 v = __ldg(ms + c);
        atomicAdd(md + c * 4 + 0, v.x);
        atomicAdd(md + c * 4 + 1, v.y);
        atomicAdd(md + c * 4 + 2, v.z);
        atomicAdd(md + c * 4 + 3, v.w);
    }
}

// ---------------------------------------------------------------------------
// GRU gate update (in place on h)
// ---------------------------------------------------------------------------
__device__ __forceinline__ float sigm_f(float x) { return 1.f / (1.f + __expf(-x)); }
__device__ __forceinline__ float tanh_f(float x) { return 1.f - 2.f / (__expf(2.f * x) + 1.f); }
__device__ __forceinline__ float gru1(float gir, float giz, float gin,
                                      float ghr, float ghz, float ghn, float h)
{
    float r = sigm_f(gir + ghr);
    float z = sigm_f(giz + ghz);
    float n = tanh_f(gin + r * ghn);
    return (1.f - z) * n + z * h;
}

__global__ void gate_k(const float* __restrict__ gi, const float* __restrict__ gh,
                       float* __restrict__ h)
{
    int idx = blockIdx.x * blockDim.x + threadIdx.x;
    if (idx >= NN * (HH / 4)) return;
    int row = idx >> 7;           // HH/4 = 128 float4 per row
    int c4  = idx & 127;
    const float4* gip = (const float4*)(gi + (size_t)row * 3 * HH) + c4;
    const float4* ghp = (const float4*)(gh + (size_t)row * 3 * HH) + c4;
    float4 gir = gip[0],   giz = gip[128], gin = gip[256];
    float4 ghr = ghp[0],   ghz = ghp[128], ghn = ghp[256];
    float4 hv = ((const float4*)h)[idx];
    float4 o;
    o.x = gru1(gir.x, giz.x, gin.x, ghr.x, ghz.x, ghn.x, hv.x);
    o.y = gru1(gir.y, giz.y, gin.y, ghr.y, ghz.y, ghn.y, hv.y);
    o.z = gru1(gir.z, giz.z, gin.z, ghr.z, ghz.z, ghn.z, hv.z);
    o.w = gru1(gir.w, giz.w, gin.w, ghr.w, ghz.w, ghn.w, hv.w);
    ((float4*)h)[idx] = o;
}

// ---------------------------------------------------------------------------
// Pooling + head
// ---------------------------------------------------------------------------
__global__ void zero_pool_k()
{
    int i = blockIdx.x * blockDim.x + threadIdx.x;
    if (i < GG * HH) g_pool[i] = 0.f;
    if (i < GG) g_cnt[i] = 0.f;
}

__global__ void pool_k(const float* __restrict__ h)
{
    int idx = blockIdx.x * blockDim.x + threadIdx.x;
    if (idx >= NN * 128) return;
    int row = idx >> 7;
    int c4  = idx & 127;
    int g   = g_batch[row];
    float4 v = ((const float4*)h)[idx];
    float* p = &g_pool[g * HH + c4 * 4];
    atomicAdd(p + 0, v.x);
    atomicAdd(p + 1, v.y);
    atomicAdd(p + 2, v.z);
    atomicAdd(p + 3, v.w);
    if (c4 == 0) atomicAdd(&g_cnt[g], 1.f);
}

__global__ void head_k(const float* __restrict__ w1, const float* __restrict__ b1,
                       const float* __restrict__ w2, const float* __restrict__ b2,
                       float* __restrict__ out)
{
    __shared__ float p[HH];
    __shared__ float red[256];
    int g = blockIdx.x, t = threadIdx.x;
    float inv = 1.f / fmaxf(g_cnt[g], 1.f);
    for (int c = t; c < HH; c += 256) p[c] = g_pool[g * HH + c] * inv;
    __syncthreads();
    float acc = b1[t];
    for (int k = 0; k < HH; k++) acc = fmaf(p[k], w1[k * 256 + t], acc);
    acc = fmaxf(acc, 0.f) * w2[t];
    red[t] = acc;
    __syncthreads();
    for (int s = 128; s > 0; s >>= 1) {
        if (t < s) red[t] += red[t + s];
        __syncthreads();
    }
    if (t == 0) out[g] = red[0] + b2[0];
}

// ---------------------------------------------------------------------------
// Launch
// ---------------------------------------------------------------------------
extern "C" void kernel_launch(void* const* d_in, const int* in_sizes, int n_in,
                              void* d_out, int out_size)
{
    const float* x       = (const float*)d_in[0];
    const void*  eidx    = d_in[1];
    const void*  batch   = d_in[2];
    const float* enc_w   = (const float*)d_in[3];
    const float* enc_b   = (const float*)d_in[4];
    const float* mlp_w1  = (const float*)d_in[5];
    const float* mlp_b1  = (const float*)d_in[6];
    const float* mlp_w2  = (const float*)d_in[7];
    const float* mlp_b2  = (const float*)d_in[8];
    const float* gru_wih = (const float*)d_in[9];
    const float* gru_whh = (const float*)d_in[10];
    const float* gru_bih = (const float*)d_in[11];
    const float* gru_bhh = (const float*)d_in[12];
    const float* head_w1 = (const float*)d_in[13];
    const float* head_b1 = (const float*)d_in[14];
    const float* head_w2 = (const float*)d_in[15];
    const float* head_b2 = (const float*)d_in[16];
    float* out = (float*)d_out;

    float *ph, *pt1, *pmsg, *pm, *pgi, *pgh;
    int *peidx, *pbatch;
    cudaGetSymbolAddress((void**)&ph,    g_h);
    cudaGetSymbolAddress((void**)&pt1,   g_t1);
    cudaGetSymbolAddress((void**)&pmsg,  g_msg);
    cudaGetSymbolAddress((void**)&pm,    g_m);
    cudaGetSymbolAddress((void**)&pgi,   g_gi);
    cudaGetSymbolAddress((void**)&pgh,   g_gh);
    cudaGetSymbolAddress((void**)&peidx, g_eidx);
    cudaGetSymbolAddress((void**)&pbatch, g_batch);

    // dtype detection + index conversion (every launch; deterministic)
    detect_k<<<1, 256>>>((const unsigned*)eidx, EE, 0);       // int32 interp: 2E/2 pairs
    detect_k<<<1, 256>>>((const unsigned*)batch, NN / 2, 1);
    convert_k<<<(2 * EE + 255) / 256, 256>>>(eidx, 2 * EE, peidx, 0);
    convert_k<<<(NN + 255) / 256, 256>>>(batch, NN, pbatch, 1);

    dim3 gEnc(HH / 128, (NN + 127) / 128);       // (4, 235)
    dim3 gGru(3 * HH / 128, (NN + 127) / 128);   // (12, 235)

    // encoder: h = x @ enc_w + enc_b
    sgemm_kernel<<<gEnc, 256>>>(x, enc_w, enc_b, ph, nullptr, NN, INC, HH, 0);

    for (int l = 0; l < LL; l++) {
        // t1 = relu(h @ w1 + b1)
        sgemm_kernel<<<gEnc, 256>>>(ph, mlp_w1 + (size_t)l * HH * HH,
                                    mlp_b1 + (size_t)l * HH, pt1, nullptr, NN, HH, HH, 1);
        // msg = t1 @ w2 + b2 ; m = msg (self-loop) via dual store
        sgemm_kernel<<<gEnc, 256>>>(pt1, mlp_w2 + (size_t)l * HH * HH,
                                    mlp_b2 + (size_t)l * HH, pmsg, pm, NN, HH, HH, 0);
        // m[dst] += msg[src]
        scatter_k<<<(EE + 7) / 8, 256>>>(pmsg, pm);
        // gi = m @ wih + bih ; gh = h @ whh + bhh
        sgemm_kernel<<<gGru, 256>>>(pm, gru_wih + (size_t)l * HH * 3 * HH,
                                    gru_bih + (size_t)l * 3 * HH, pgi, nullptr, NN, HH, 3 * HH, 0);
        sgemm_kernel<<<gGru, 256>>>(ph, gru_whh + (size_t)l * HH * 3 * HH,
                                    gru_bhh + (size_t)l * 3 * HH, pgh, nullptr, NN, HH, 3 * HH, 0);
        // h = GRU(h, m)
        gate_k<<<(NN * 128 + 255) / 256, 256>>>(pgi, pgh, ph);
    }

    // global mean pool + head
    zero_pool_k<<<(GG * HH + 255) / 256, 256>>>();
    pool_k<<<(NN * 128 + 255) / 256, 256>>>(ph);
    head_k<<<GG, 256>>>(head_w1, head_b1, head_w2, head_b2, out);
}

// round 8
// speedup vs baseline: 1.4953x; 1.4953x over previous
#include <cuda_runtime.h>
#include <cstdint>

// Problem constants
#define NN   30000
#define EE   480000
#define GG   64
#define INC  24
#define HH   512
#define LL   6

// ---------------------------------------------------------------------------
// Scratch (device globals — no allocations allowed anywhere)
// ---------------------------------------------------------------------------
__device__ __align__(16) float g_h  [(size_t)NN * HH];        // node state
__device__ __align__(16) float g_t1 [(size_t)NN * HH];        // MLP hidden
__device__ __align__(16) float g_msg[(size_t)NN * HH];        // per-node message
__device__ __align__(16) float g_m  [(size_t)NN * HH];        // aggregated message
__device__ __align__(16) float g_gi [(size_t)NN * 3 * HH];    // GRU input gates
__device__ __align__(16) float g_gh [(size_t)NN * 3 * HH];    // GRU hidden gates
__device__ __align__(16) float g_pool[GG * HH];
__device__ float g_cnt [GG];
__device__ int   g_eidx[2 * EE];                // converted edge index (int32)
__device__ int   g_batch[NN];                   // converted batch (int32)
__device__ int   g_flag[2];                     // dtype flags: [0]=edges, [1]=batch

// ---------------------------------------------------------------------------
// dtype detection: int64 buffers (values < 2^31) have all odd 32-bit words == 0
// ---------------------------------------------------------------------------
__global__ void detect_k(const unsigned* __restrict__ p, int pairs, int slot)
{
    __shared__ int any;
    if (threadIdx.x == 0) any = 0;
    __syncthreads();
    int lim = pairs < 8192 ? pairs : 8192;
    for (int i = threadIdx.x; i < lim; i += blockDim.x)
        if (p[2 * i + 1] != 0u) any = 1;
    __syncthreads();
    if (threadIdx.x == 0) g_flag[slot] = (any == 0) ? 1 : 0;
}

__global__ void convert_k(const void* __restrict__ in, int n, int* __restrict__ out, int slot)
{
    int i = blockIdx.x * blockDim.x + threadIdx.x;
    if (i >= n) return;
    if (g_flag[slot])
        out[i] = (int)(((const long long*)in)[i]);
    else
        out[i] = ((const int*)in)[i];
}

// ---------------------------------------------------------------------------
// 3xTF32 tensor-core GEMM: C[M,Nc] = act(A[M,K] @ W[K,Nc] + bias)
// Each fp32 operand is split x = hi + lo (both tf32); accumulate
// hi*hi + lo*hi + hi*lo -> effective precision ~2^-22 per product.
// BM=128, BN=256, BK=32, 3-stage cp.async pipeline, 256 threads,
// 8 warps in 2(m) x 4(n), warp tile 64x64, mma.m16n8k8.tf32.
// Requires K % 32 == 0, Nc % 256 == 0.
// ---------------------------------------------------------------------------
#define BM 128
#define BN 256
#define BK 32
#define STAGES 3
#define AS_STRIDE 36              // 32 + 4 pad
#define BS_STRIDE 264             // 256 + 8 pad
#define A_FLOATS (BM * AS_STRIDE) // 4608
#define B_FLOATS (BK * BS_STRIDE) // 8448
#define STAGE_FLOATS (A_FLOATS + B_FLOATS)
#define GEMM_SMEM_BYTES (STAGES * STAGE_FLOATS * 4)  // 156,672 B

__device__ __forceinline__ void cp_async16(float* s, const float* g, bool pred)
{
    unsigned saddr = (unsigned)__cvta_generic_to_shared(s);
    int sz = pred ? 16 : 0;
    asm volatile("cp.async.cg.shared.global [%0], [%1], 16, %2;\n"
                 :: "r"(saddr), "l"(g), "r"(sz));
}

__device__ __forceinline__ uint32_t f2tf32(float f)
{
    uint32_t u;
    asm("cvt.rna.tf32.f32 %0, %1;" : "=r"(u) : "f"(f));
    return u;
}

// x = hi + lo decomposition; both tf32-representable fp32 bit patterns
__device__ __forceinline__ void split_tf32(float v, uint32_t& hi, uint32_t& lo)
{
    hi = f2tf32(v);
    lo = f2tf32(v - __uint_as_float(hi));
}

__device__ __forceinline__ void mma_tf32(float* d, const uint32_t* a, const uint32_t* b)
{
    asm volatile(
        "mma.sync.aligned.m16n8k8.row.col.f32.tf32.tf32.f32 "
        "{%0,%1,%2,%3}, {%4,%5,%6,%7}, {%8,%9}, {%0,%1,%2,%3};"
        : "+f"(d[0]), "+f"(d[1]), "+f"(d[2]), "+f"(d[3])
        : "r"(a[0]), "r"(a[1]), "r"(a[2]), "r"(a[3]), "r"(b[0]), "r"(b[1]));
}

__device__ __forceinline__ void load_stage(float* sbase,
                                           const float* __restrict__ A,
                                           const float* __restrict__ W,
                                           int M, int K, int Nc,
                                           int bm, int bn, int k0, int tid)
{
    float* As = sbase;
    float* Bs = sbase + A_FLOATS;
    // A: 128 rows x 8 float4 (row-major global [m][k])
    int arow = tid >> 1;
    int ak4  = (tid & 1) * 4;          // float4 index 0 or 4
    const float* ag = A + (size_t)(bm + arow) * K + k0 + ak4 * 4;
    float* as = As + arow * AS_STRIDE + ak4 * 4;
    bool av = (bm + arow) < M;
#pragma unroll
    for (int i = 0; i < 4; i++)
        cp_async16(as + i * 4, ag + i * 4, av);
    // B: 32 rows x 64 float4 (global [k][n])
    int brow = tid >> 3;
    int bc   = tid & 7;
    const float* bg = W + (size_t)(k0 + brow) * Nc + bn + bc * 4;
    float* bs = Bs + brow * BS_STRIDE + bc * 4;
#pragma unroll
    for (int j = 0; j < 8; j++)
        cp_async16(bs + j * 32, bg + j * 32, true);
}

__global__ __launch_bounds__(256, 1)
void tf32gemm(const float* __restrict__ A, const float* __restrict__ W,
              const float* __restrict__ bias, float* __restrict__ C,
              float* __restrict__ C2, int M, int K, int Nc, int do_relu)
{
    extern __shared__ float smem[];
    const int tid  = threadIdx.x;
    const int bm   = blockIdx.y * BM;
    const int bn   = blockIdx.x * BN;
    const int warp = tid >> 5, lane = tid & 31;
    const int wm   = (warp >> 2) * 64;   // 0 or 64
    const int wn   = (warp & 3) * 64;    // 0,64,128,192
    const int gid  = lane >> 2, tig = lane & 3;

    float acc[4][8][4];
#pragma unroll
    for (int mt = 0; mt < 4; mt++)
#pragma unroll
        for (int nt = 0; nt < 8; nt++)
#pragma unroll
            for (int r = 0; r < 4; r++) acc[mt][nt][r] = 0.f;

    const int kTiles = K / BK;

    load_stage(smem, A, W, M, K, Nc, bm, bn, 0, tid);
    asm volatile("cp.async.commit_group;\n");
    load_stage(smem + STAGE_FLOATS, A, W, M, K, Nc, bm, bn, BK, tid);
    asm volatile("cp.async.commit_group;\n");
    asm volatile("cp.async.wait_group 1;\n");
    __syncthreads();

    for (int kt = 0; kt < kTiles; kt++) {
        float* As = smem + (kt % STAGES) * STAGE_FLOATS;
        float* Bs = As + A_FLOATS;

        if (kt + 2 < kTiles)
            load_stage(smem + ((kt + 2) % STAGES) * STAGE_FLOATS,
                       A, W, M, K, Nc, bm, bn, (kt + 2) * BK, tid);
        asm volatile("cp.async.commit_group;\n");

#pragma unroll
        for (int ks = 0; ks < 4; ks++) {
            const int c0 = ks * 8 + tig, c1 = c0 + 4;
            // A fragments: hi + lo resident for all 4 m-tiles
            uint32_t ah[4][4], al[4][4];
#pragma unroll
            for (int mt = 0; mt < 4; mt++) {
                int r0 = wm + mt * 16 + gid;
                split_tf32(As[r0 * AS_STRIDE + c0],       ah[mt][0], al[mt][0]);
                split_tf32(As[(r0 + 8) * AS_STRIDE + c0], ah[mt][1], al[mt][1]);
                split_tf32(As[r0 * AS_STRIDE + c1],       ah[mt][2], al[mt][2]);
                split_tf32(As[(r0 + 8) * AS_STRIDE + c1], ah[mt][3], al[mt][3]);
            }
            // B fragments: split on the fly per n-tile (keeps regs low)
#pragma unroll
            for (int nt = 0; nt < 8; nt++) {
                int col = wn + nt * 8 + gid;
                uint32_t bh[2], bl[2];
                split_tf32(Bs[c0 * BS_STRIDE + col], bh[0], bl[0]);
                split_tf32(Bs[c1 * BS_STRIDE + col], bh[1], bl[1]);
#pragma unroll
                for (int mt = 0; mt < 4; mt++) {
                    mma_tf32(acc[mt][nt], ah[mt], bh);   // hi*hi
                    mma_tf32(acc[mt][nt], al[mt], bh);   // lo*hi
                    mma_tf32(acc[mt][nt], ah[mt], bl);   // hi*lo
                }
            }
        }

        asm volatile("cp.async.wait_group 1;\n");
        __syncthreads();
    }

    // Epilogue: bias (+relu), store float2; optional dual store (self-loop init)
#pragma unroll
    for (int nt = 0; nt < 8; nt++) {
        int col = bn + wn + nt * 8 + tig * 2;
        float b0 = bias[col], b1 = bias[col + 1];
#pragma unroll
        for (int mt = 0; mt < 4; mt++) {
            int r0 = bm + wm + mt * 16 + gid;
            int r1 = r0 + 8;
            float v0 = acc[mt][nt][0] + b0;
            float v1 = acc[mt][nt][1] + b1;
            float v2 = acc[mt][nt][2] + b0;
            float v3 = acc[mt][nt][3] + b1;
            if (do_relu) {
                v0 = fmaxf(v0, 0.f); v1 = fmaxf(v1, 0.f);
                v2 = fmaxf(v2, 0.f); v3 = fmaxf(v3, 0.f);
            }
            if (r0 < M) {
                *(float2*)(C + (size_t)r0 * Nc + col) = make_float2(v0, v1);
                if (C2) *(float2*)(C2 + (size_t)r0 * Nc + col) = make_float2(v0, v1);
            }
            if (r1 < M) {
                *(float2*)(C + (size_t)r1 * Nc + col) = make_float2(v2, v3);
                if (C2) *(float2*)(C2 + (size_t)r1 * Nc + col) = make_float2(v2, v3);
            }
        }
    }
}

// ---------------------------------------------------------------------------
// SIMT SGEMM (kept for encoder only, K=24): C = A@W + bias
// ---------------------------------------------------------------------------
__global__ __launch_bounds__(256, 2)
void sgemm_kernel(const float* __restrict__ A, const float* __restrict__ W,
                  const float* __restrict__ bias, float* __restrict__ C,
                  int M, int K, int Nc)
{
    __shared__ float As[2][8][128];
    __shared__ float Bs[2][8][128];

    const int tid = threadIdx.x;
    const int bm = blockIdx.y * 128;
    const int bn = blockIdx.x * 128;

    const int arow = tid >> 1;
    const int acol = (tid & 1) << 2;
    const int brow = tid >> 5;
    const int bcol = (tid & 31) << 2;
    const int ty = tid >> 4;
    const int tx = tid & 15;

    float acc[8][8];
#pragma unroll
    for (int i = 0; i < 8; i++)
#pragma unroll
        for (int j = 0; j < 8; j++) acc[i][j] = 0.f;

    const int grow = bm + arow;
    const float* Arow = A + (size_t)grow * K;

    float4 av, bv;
    av = (grow < M) ? *(const float4*)(Arow + acol) : make_float4(0.f, 0.f, 0.f, 0.f);
    bv = *(const float4*)(W + (size_t)brow * Nc + bn + bcol);
    As[0][acol + 0][arow] = av.x; As[0][acol + 1][arow] = av.y;
    As[0][acol + 2][arow] = av.z; As[0][acol + 3][arow] = av.w;
    *(float4*)&Bs[0][brow][bcol] = bv;
    __syncthreads();

    int buf = 0;
    for (int k0 = 0; k0 < K; k0 += 8) {
        const bool next = (k0 + 8) < K;
        if (next) {
            av = (grow < M) ? *(const float4*)(Arow + k0 + 8 + acol)
                            : make_float4(0.f, 0.f, 0.f, 0.f);
            bv = *(const float4*)(W + (size_t)(k0 + 8 + brow) * Nc + bn + bcol);
        }
#pragma unroll
        for (int kk = 0; kk < 8; kk++) {
            float4 a0 = *(const float4*)&As[buf][kk][ty * 8];
            float4 a1 = *(const float4*)&As[buf][kk][ty * 8 + 4];
            float4 b0 = *(const float4*)&Bs[buf][kk][tx * 8];
            float4 b1 = *(const float4*)&Bs[buf][kk][tx * 8 + 4];
            float a[8] = {a0.x, a0.y, a0.z, a0.w, a1.x, a1.y, a1.z, a1.w};
            float b[8] = {b0.x, b0.y, b0.z, b0.w, b1.x, b1.y, b1.z, b1.w};
#pragma unroll
            for (int i = 0; i < 8; i++)
#pragma unroll
                for (int j = 0; j < 8; j++)
                    acc[i][j] = fmaf(a[i], b[j], acc[i][j]);
        }
        if (next) {
            const int nbuf = buf ^ 1;
            As[nbuf][acol + 0][arow] = av.x; As[nbuf][acol + 1][arow] = av.y;
            As[nbuf][acol + 2][arow] = av.z; As[nbuf][acol + 3][arow] = av.w;
            *(float4*)&Bs[nbuf][brow][bcol] = bv;
            __syncthreads();
            buf = nbuf;
        }
    }

    float bvals[8];
#pragma unroll
    for (int j = 0; j < 8; j++) bvals[j] = bias[bn + tx * 8 + j];
#pragma unroll
    for (int i = 0; i < 8; i++) {
        int row = bm + ty * 8 + i;
        if (row >= M) continue;
        float o[8];
#pragma unroll
        for (int j = 0; j < 8; j++) o[j] = acc[i][j] + bvals[j];
        float4* cp = (float4*)(C + (size_t)row * Nc + bn + tx * 8);
        cp[0] = make_float4(o[0], o[1], o[2], o[3]);
        cp[1] = make_float4(o[4], o[5], o[6], o[7]);
    }
}

// ---------------------------------------------------------------------------
// Edge scatter: m[dst] += msg[src]  (warp/edge, vector red.global.v4.f32)
// ---------------------------------------------------------------------------
__global__ void scatter_k(const float* __restrict__ msg, float* __restrict__ m)
{
    int gw = (blockIdx.x * blockDim.x + threadIdx.x) >> 5;
    int lane = threadIdx.x & 31;
    if (gw >= EE) return;
    int s = g_eidx[gw];
    int d = g_eidx[EE + gw];
    const float4* ms = (const float4*)(msg + (size_t)s * HH);
    float4* md = (float4*)(m + (size_t)d * HH);
#pragma unroll
    for (int i = 0; i < 4; i++) {
        int c = lane + i * 32;                // float4 index 0..127
        float4 v = __ldg(ms + c);
        asm volatile("red.global.add.v4.f32 [%0], {%1,%2,%3,%4};"
                     :: "l"(md + c), "f"(v.x), "f"(v.y), "f"(v.z), "f"(v.w)
                     : "memory");
    }
}

// ---------------------------------------------------------------------------
// GRU gate update (in place on h)
// ---------------------------------------------------------------------------
__device__ __forceinline__ float sigm_f(float x) { return 1.f / (1.f + __expf(-x)); }
__device__ __forceinline__ float tanh_f(float x) { return 1.f - 2.f / (__expf(2.f * x) + 1.f); }
__device__ __forceinline__ float gru1(float gir, float giz, float gin,
                                      float ghr, float ghz, float ghn, float h)
{
    float r = sigm_f(gir + ghr);
    float z = sigm_f(giz + ghz);
    float n = tanh_f(gin + r * ghn);
    return (1.f - z) * n + z * h;
}

__global__ void gate_k(const float* __restrict__ gi, const float* __restrict__ gh,
                       float* __restrict__ h)
{
    int idx = blockIdx.x * blockDim.x + threadIdx.x;
    if (idx >= NN * (HH / 4)) return;
    int row = idx >> 7;
    int c4  = idx & 127;
    const float4* gip = (const float4*)(gi + (size_t)row * 3 * HH) + c4;
    const float4* ghp = (const float4*)(gh + (size_t)row * 3 * HH) + c4;
    float4 gir = gip[0],   giz = gip[128], gin = gip[256];
    float4 ghr = ghp[0],   ghz = ghp[128], ghn = ghp[256];
    float4 hv = ((const float4*)h)[idx];
    float4 o;
    o.x = gru1(gir.x, giz.x, gin.x, ghr.x, ghz.x, ghn.x, hv.x);
    o.y = gru1(gir.y, giz.y, gin.y, ghr.y, ghz.y, ghn.y, hv.y);
    o.z = gru1(gir.z, giz.z, gin.z, ghr.z, ghz.z, ghn.z, hv.z);
    o.w = gru1(gir.w, giz.w, gin.w, ghr.w, ghz.w, ghn.w, hv.w);
    ((float4*)h)[idx] = o;
}

// ---------------------------------------------------------------------------
// Pooling + head
// ---------------------------------------------------------------------------
__global__ void zero_pool_k()
{
    int i = blockIdx.x * blockDim.x + threadIdx.x;
    if (i < GG * HH) g_pool[i] = 0.f;
    if (i < GG) g_cnt[i] = 0.f;
}

__global__ void pool_k(const float* __restrict__ h)
{
    int idx = blockIdx.x * blockDim.x + threadIdx.x;
    if (idx >= NN * 128) return;
    int row = idx >> 7;
    int c4  = idx & 127;
    int g   = g_batch[row];
    float4 v = ((const float4*)h)[idx];
    float* p = &g_pool[g * HH + c4 * 4];
    asm volatile("red.global.add.v4.f32 [%0], {%1,%2,%3,%4};"
                 :: "l"(p), "f"(v.x), "f"(v.y), "f"(v.z), "f"(v.w)
                 : "memory");
    if (c4 == 0) atomicAdd(&g_cnt[g], 1.f);
}

__global__ void head_k(const float* __restrict__ w1, const float* __restrict__ b1,
                       const float* __restrict__ w2, const float* __restrict__ b2,
                       float* __restrict__ out)
{
    __shared__ float p[HH];
    __shared__ float red[256];
    int g = blockIdx.x, t = threadIdx.x;
    float inv = 1.f / fmaxf(g_cnt[g], 1.f);
    for (int c = t; c < HH; c += 256) p[c] = g_pool[g * HH + c] * inv;
    __syncthreads();
    float acc = b1[t];
    for (int k = 0; k < HH; k++) acc = fmaf(p[k], w1[k * 256 + t], acc);
    acc = fmaxf(acc, 0.f) * w2[t];
    red[t] = acc;
    __syncthreads();
    for (int s = 128; s > 0; s >>= 1) {
        if (t < s) red[t] += red[t + s];
        __syncthreads();
    }
    if (t == 0) out[g] = red[0] + b2[0];
}

// ---------------------------------------------------------------------------
// Launch
// ---------------------------------------------------------------------------
extern "C" void kernel_launch(void* const* d_in, const int* in_sizes, int n_in,
                              void* d_out, int out_size)
{
    const float* x       = (const float*)d_in[0];
    const void*  eidx    = d_in[1];
    const void*  batch   = d_in[2];
    const float* enc_w   = (const float*)d_in[3];
    const float* enc_b   = (const float*)d_in[4];
    const float* mlp_w1  = (const float*)d_in[5];
    const float* mlp_b1  = (const float*)d_in[6];
    const float* mlp_w2  = (const float*)d_in[7];
    const float* mlp_b2  = (const float*)d_in[8];
    const float* gru_wih = (const float*)d_in[9];
    const float* gru_whh = (const float*)d_in[10];
    const float* gru_bih = (const float*)d_in[11];
    const float* gru_bhh = (const float*)d_in[12];
    const float* head_w1 = (const float*)d_in[13];
    const float* head_b1 = (const float*)d_in[14];
    const float* head_w2 = (const float*)d_in[15];
    const float* head_b2 = (const float*)d_in[16];
    float* out = (float*)d_out;

    float *ph, *pt1, *pmsg, *pm, *pgi, *pgh;
    int *peidx, *pbatch;
    cudaGetSymbolAddress((void**)&ph,    g_h);
    cudaGetSymbolAddress((void**)&pt1,   g_t1);
    cudaGetSymbolAddress((void**)&pmsg,  g_msg);
    cudaGetSymbolAddress((void**)&pm,    g_m);
    cudaGetSymbolAddress((void**)&pgi,   g_gi);
    cudaGetSymbolAddress((void**)&pgh,   g_gh);
    cudaGetSymbolAddress((void**)&peidx, g_eidx);
    cudaGetSymbolAddress((void**)&pbatch, g_batch);

    cudaFuncSetAttribute(tf32gemm, cudaFuncAttributeMaxDynamicSharedMemorySize,
                         GEMM_SMEM_BYTES);

    // dtype detection + index conversion (every launch; deterministic)
    detect_k<<<1, 256>>>((const unsigned*)eidx, EE, 0);
    detect_k<<<1, 256>>>((const unsigned*)batch, NN / 2, 1);
    convert_k<<<(2 * EE + 255) / 256, 256>>>(eidx, 2 * EE, peidx, 0);
    convert_k<<<(NN + 255) / 256, 256>>>(batch, NN, pbatch, 1);

    dim3 gEnc(HH / 128, (NN + 127) / 128);                 // SIMT encoder grid
    dim3 gMsg(HH / BN, (NN + BM - 1) / BM);                // (2, 235)
    dim3 gGru(3 * HH / BN, (NN + BM - 1) / BM);            // (6, 235)

    // encoder: h = x @ enc_w + enc_b (K=24, SIMT, exact fp32)
    sgemm_kernel<<<gEnc, 256>>>(x, enc_w, enc_b, ph, NN, INC, HH);

    for (int l = 0; l < LL; l++) {
        // t1 = relu(h @ w1 + b1)
        tf32gemm<<<gMsg, 256, GEMM_SMEM_BYTES>>>(
            ph, mlp_w1 + (size_t)l * HH * HH, mlp_b1 + (size_t)l * HH,
            pt1, nullptr, NN, HH, HH, 1);
        // msg = t1 @ w2 + b2 ; m = msg (self-loop) via dual store
        tf32gemm<<<gMsg, 256, GEMM_SMEM_BYTES>>>(
            pt1, mlp_w2 + (size_t)l * HH * HH, mlp_b2 + (size_t)l * HH,
            pmsg, pm, NN, HH, HH, 0);
        // m[dst] += msg[src]
        scatter_k<<<(EE + 7) / 8, 256>>>(pmsg, pm);
        // gi = m @ wih + bih ; gh = h @ whh + bhh
        tf32gemm<<<gGru, 256, GEMM_SMEM_BYTES>>>(
            pm, gru_wih + (size_t)l * HH * 3 * HH, gru_bih + (size_t)l * 3 * HH,
            pgi, nullptr, NN, HH, 3 * HH, 0);
        tf32gemm<<<gGru, 256, GEMM_SMEM_BYTES>>>(
            ph, gru_whh + (size_t)l * HH * 3 * HH, gru_bhh + (size_t)l * 3 * HH,
            pgh, nullptr, NN, HH, 3 * HH, 0);
        // h = GRU(h, m)
        gate_k<<<(NN * 128 + 255) / 256, 256>>>(pgi, pgh, ph);
    }

    // global mean pool + head
    zero_pool_k<<<(GG * HH + 255) / 256, 256>>>();
    pool_k<<<(NN * 128 + 255) / 256, 256>>>(ph);
    head_k<<<GG, 256>>>(head_w1, head_b1, head_w2, head_b2, out);
}

// round 10
// speedup vs baseline: 1.5305x; 1.0236x over previous
#include <cuda_runtime.h>
#include <cstdint>

// Problem constants
#define NN   30000
#define EE   480000
#define GG   64
#define INC  24
#define HH   512
#define LL   6

// ---------------------------------------------------------------------------
// Scratch (device globals — no allocations allowed anywhere)
// ---------------------------------------------------------------------------
__device__ __align__(16) float g_h  [(size_t)NN * HH];        // node state
__device__ __align__(16) float g_t1 [(size_t)NN * HH];        // MLP hidden
__device__ __align__(16) float g_msg[(size_t)NN * HH];        // per-node message
__device__ __align__(16) float g_m  [(size_t)NN * HH];        // aggregated message
__device__ __align__(16) float g_gi [(size_t)NN * 3 * HH];    // GRU input gates
__device__ __align__(16) float g_gh [(size_t)NN * 3 * HH];    // GRU hidden gates
__device__ __align__(16) float g_pool[GG * HH];
__device__ float g_cnt [GG];
__device__ int   g_eidx[2 * EE];                // converted edge index (int32)
__device__ int   g_batch[NN];                   // converted batch (int32)
__device__ int   g_flag[2];                     // dtype flags: [0]=edges, [1]=batch

// ---------------------------------------------------------------------------
// dtype detection (one kernel, block 0 = edges, block 1 = batch):
// int64 buffers (values < 2^31) have all odd 32-bit words == 0
// ---------------------------------------------------------------------------
__global__ void detect_both_k(const unsigned* __restrict__ pe,
                              const unsigned* __restrict__ pb)
{
    __shared__ int any;
    if (threadIdx.x == 0) any = 0;
    __syncthreads();
    const unsigned* p = (blockIdx.x == 0) ? pe : pb;
    int pairs = (blockIdx.x == 0) ? EE : (NN / 2);
    int lim = pairs < 8192 ? pairs : 8192;
    for (int i = threadIdx.x; i < lim; i += blockDim.x)
        if (p[2 * i + 1] != 0u) any = 1;
    __syncthreads();
    if (threadIdx.x == 0) g_flag[blockIdx.x] = (any == 0) ? 1 : 0;
}

// one kernel converts both arrays (edges then batch)
__global__ void convert_both_k(const void* __restrict__ e, const void* __restrict__ b)
{
    int i = blockIdx.x * blockDim.x + threadIdx.x;
    if (i < 2 * EE) {
        g_eidx[i] = g_flag[0] ? (int)(((const long long*)e)[i])
                              : ((const int*)e)[i];
    } else if (i < 2 * EE + NN) {
        int j = i - 2 * EE;
        g_batch[j] = g_flag[1] ? (int)(((const long long*)b)[j])
                               : ((const int*)b)[j];
    }
}

// ---------------------------------------------------------------------------
// 3xTF32 tensor-core GEMM: C[M,Nc] = act(A[M,K] @ W[K,Nc] + bias)
// Each fp32 operand is split x = hi + lo (both tf32); accumulate
// hi*hi + lo*hi + hi*lo -> effective precision ~2^-22 per product.
// BM=128, BN=128, BK=32, 3-stage cp.async pipeline, 256 threads,
// 8 warps in 2(m) x 4(n), warp tile 64x32, mma.m16n8k8.tf32.
// 2 CTAs/SM (smem 105KB/CTA, <=128 regs). Requires K%32==0, Nc%128==0.
// ---------------------------------------------------------------------------
#define BM 128
#define BN 128
#define BK 32
#define STAGES 3
#define AS_STRIDE 36              // 32 + 4 pad (bank 4*gid+tig, conflict-free)
#define BS_STRIDE 136             // 128 + 8 pad (bank 8*tig+gid, conflict-free)
#define A_FLOATS (BM * AS_STRIDE) // 4608
#define B_FLOATS (BK * BS_STRIDE) // 4352
#define STAGE_FLOATS (A_FLOATS + B_FLOATS)                 // 8960
#define GEMM_SMEM_BYTES (STAGES * STAGE_FLOATS * 4)        // 107,520 B

__device__ __forceinline__ void cp_async16(float* s, const float* g, bool pred)
{
    unsigned saddr = (unsigned)__cvta_generic_to_shared(s);
    int sz = pred ? 16 : 0;
    asm volatile("cp.async.cg.shared.global [%0], [%1], 16, %2;\n"
                 :: "r"(saddr), "l"(g), "r"(sz));
}

__device__ __forceinline__ uint32_t f2tf32(float f)
{
    uint32_t u;
    asm("cvt.rna.tf32.f32 %0, %1;" : "=r"(u) : "f"(f));
    return u;
}

// x = hi + lo decomposition; both tf32-representable fp32 bit patterns
__device__ __forceinline__ void split_tf32(float v, uint32_t& hi, uint32_t& lo)
{
    hi = f2tf32(v);
    lo = f2tf32(v - __uint_as_float(hi));
}

__device__ __forceinline__ void mma_tf32(float* d, const uint32_t* a, const uint32_t* b)
{
    asm volatile(
        "mma.sync.aligned.m16n8k8.row.col.f32.tf32.tf32.f32 "
        "{%0,%1,%2,%3}, {%4,%5,%6,%7}, {%8,%9}, {%0,%1,%2,%3};"
        : "+f"(d[0]), "+f"(d[1]), "+f"(d[2]), "+f"(d[3])
        : "r"(a[0]), "r"(a[1]), "r"(a[2]), "r"(a[3]), "r"(b[0]), "r"(b[1]));
}

__device__ __forceinline__ void load_stage(float* sbase,
                                           const float* __restrict__ A,
                                           const float* __restrict__ W,
                                           int M, int K, int Nc,
                                           int bm, int bn, int k0, int tid)
{
    float* As = sbase;
    float* Bs = sbase + A_FLOATS;
    // A: 128 rows x 8 float4 (row-major global [m][k]); 4 f4 per thread
    int arow = tid >> 1;
    int ak4  = (tid & 1) * 4;          // float4 index 0 or 4
    const float* ag = A + (size_t)(bm + arow) * K + k0 + ak4 * 4;
    float* as = As + arow * AS_STRIDE + ak4 * 4;
    bool av = (bm + arow) < M;
#pragma unroll
    for (int i = 0; i < 4; i++)
        cp_async16(as + i * 4, ag + i * 4, av);
    // B: 32 rows x 32 float4 (global [k][n]); 4 f4 per thread
    int brow = tid >> 3;               // 0..31
    int bc   = tid & 7;                // 0..7
    const float* bg = W + (size_t)(k0 + brow) * Nc + bn + bc * 4;
    float* bs = Bs + brow * BS_STRIDE + bc * 4;
#pragma unroll
    for (int j = 0; j < 4; j++)
        cp_async16(bs + j * 32, bg + j * 32, true);
}

__global__ __launch_bounds__(256, 2)
void tf32gemm(const float* __restrict__ A, const float* __restrict__ W,
              const float* __restrict__ bias, float* __restrict__ C,
              float* __restrict__ C2, int M, int K, int Nc, int do_relu)
{
    extern __shared__ float smem[];
    const int tid  = threadIdx.x;
    const int bm   = blockIdx.y * BM;
    const int bn   = blockIdx.x * BN;
    const int warp = tid >> 5, lane = tid & 31;
    const int wm   = (warp >> 2) * 64;   // 0 or 64
    const int wn   = (warp & 3) * 32;    // 0,32,64,96
    const int gid  = lane >> 2, tig = lane & 3;

    float acc[4][4][4];
#pragma unroll
    for (int mt = 0; mt < 4; mt++)
#pragma unroll
        for (int nt = 0; nt < 4; nt++)
#pragma unroll
            for (int r = 0; r < 4; r++) acc[mt][nt][r] = 0.f;

    const int kTiles = K / BK;

    load_stage(smem, A, W, M, K, Nc, bm, bn, 0, tid);
    asm volatile("cp.async.commit_group;\n");
    load_stage(smem + STAGE_FLOATS, A, W, M, K, Nc, bm, bn, BK, tid);
    asm volatile("cp.async.commit_group;\n");
    asm volatile("cp.async.wait_group 1;\n");
    __syncthreads();

    for (int kt = 0; kt < kTiles; kt++) {
        float* As = smem + (kt % STAGES) * STAGE_FLOATS;
        float* Bs = As + A_FLOATS;

        if (kt + 2 < kTiles)
            load_stage(smem + ((kt + 2) % STAGES) * STAGE_FLOATS,
                       A, W, M, K, Nc, bm, bn, (kt + 2) * BK, tid);
        asm volatile("cp.async.commit_group;\n");

#pragma unroll
        for (int ks = 0; ks < 4; ks++) {
            const int c0 = ks * 8 + tig, c1 = c0 + 4;
            // A fragments: hi + lo resident for all 4 m-tiles
            uint32_t ah[4][4], al[4][4];
#pragma unroll
            for (int mt = 0; mt < 4; mt++) {
                int r0 = wm + mt * 16 + gid;
                split_tf32(As[r0 * AS_STRIDE + c0],       ah[mt][0], al[mt][0]);
                split_tf32(As[(r0 + 8) * AS_STRIDE + c0], ah[mt][1], al[mt][1]);
                split_tf32(As[r0 * AS_STRIDE + c1],       ah[mt][2], al[mt][2]);
                split_tf32(As[(r0 + 8) * AS_STRIDE + c1], ah[mt][3], al[mt][3]);
            }
            // B fragments: split on the fly per n-tile
#pragma unroll
            for (int nt = 0; nt < 4; nt++) {
                int col = wn + nt * 8 + gid;
                uint32_t bh[2], bl[2];
                split_tf32(Bs[c0 * BS_STRIDE + col], bh[0], bl[0]);
                split_tf32(Bs[c1 * BS_STRIDE + col], bh[1], bl[1]);
#pragma unroll
                for (int mt = 0; mt < 4; mt++) {
                    mma_tf32(acc[mt][nt], ah[mt], bh);   // hi*hi
                    mma_tf32(acc[mt][nt], al[mt], bh);   // lo*hi
                    mma_tf32(acc[mt][nt], ah[mt], bl);   // hi*lo
                }
            }
        }

        asm volatile("cp.async.wait_group 1;\n");
        __syncthreads();
    }

    // Epilogue: bias (+relu), store float2; optional dual store (self-loop init)
#pragma unroll
    for (int nt = 0; nt < 4; nt++) {
        int col = bn + wn + nt * 8 + tig * 2;
        float b0 = bias[col], b1 = bias[col + 1];
#pragma unroll
        for (int mt = 0; mt < 4; mt++) {
            int r0 = bm + wm + mt * 16 + gid;
            int r1 = r0 + 8;
            float v0 = acc[mt][nt][0] + b0;
            float v1 = acc[mt][nt][1] + b1;
            float v2 = acc[mt][nt][2] + b0;
            float v3 = acc[mt][nt][3] + b1;
            if (do_relu) {
                v0 = fmaxf(v0, 0.f); v1 = fmaxf(v1, 0.f);
                v2 = fmaxf(v2, 0.f); v3 = fmaxf(v3, 0.f);
            }
            if (r0 < M) {
                *(float2*)(C + (size_t)r0 * Nc + col) = make_float2(v0, v1);
                if (C2) *(float2*)(C2 + (size_t)r0 * Nc + col) = make_float2(v0, v1);
            }
            if (r1 < M) {
                *(float2*)(C + (size_t)r1 * Nc + col) = make_float2(v2, v3);
                if (C2) *(float2*)(C2 + (size_t)r1 * Nc + col) = make_float2(v2, v3);
            }
        }
    }
}

// ---------------------------------------------------------------------------
// SIMT SGEMM (kept for encoder only, K=24): C = A@W + bias
// ---------------------------------------------------------------------------
__global__ __launch_bounds__(256, 2)
void sgemm_kernel(const float* __restrict__ A, const float* __restrict__ W,
                  const float* __restrict__ bias, float* __restrict__ C,
                  int M, int K, int Nc)
{
    __shared__ float As[2][8][128];
    __shared__ float Bs[2][8][128];

    const int tid = threadIdx.x;
    const int bm = blockIdx.y * 128;
    const int bn = blockIdx.x * 128;

    const int arow = tid >> 1;
    const int acol = (tid & 1) << 2;
    const int brow = tid >> 5;
    const int bcol = (tid & 31) << 2;
    const int ty = tid >> 4;
    const int tx = tid & 15;

    float acc[8][8];
#pragma unroll
    for (int i = 0; i < 8; i++)
#pragma unroll
        for (int j = 0; j < 8; j++) acc[i][j] = 0.f;

    const int grow = bm + arow;
    const float* Arow = A + (size_t)grow * K;

    float4 av, bv;
    av = (grow < M) ? *(const float4*)(Arow + acol) : make_float4(0.f, 0.f, 0.f, 0.f);
    bv = *(const float4*)(W + (size_t)brow * Nc + bn + bcol);
    As[0][acol + 0][arow] = av.x; As[0][acol + 1][arow] = av.y;
    As[0][acol + 2][arow] = av.z; As[0][acol + 3][arow] = av.w;
    *(float4*)&Bs[0][brow][bcol] = bv;
    __syncthreads();

    int buf = 0;
    for (int k0 = 0; k0 < K; k0 += 8) {
        const bool next = (k0 + 8) < K;
        if (next) {
            av = (grow < M) ? *(const float4*)(Arow + k0 + 8 + acol)
                            : make_float4(0.f, 0.f, 0.f, 0.f);
            bv = *(const float4*)(W + (size_t)(k0 + 8 + brow) * Nc + bn + bcol);
        }
#pragma unroll
        for (int kk = 0; kk < 8; kk++) {
            float4 a0 = *(const float4*)&As[buf][kk][ty * 8];
            float4 a1 = *(const float4*)&As[buf][kk][ty * 8 + 4];
            float4 b0 = *(const float4*)&Bs[buf][kk][tx * 8];
            float4 b1 = *(const float4*)&Bs[buf][kk][tx * 8 + 4];
            float a[8] = {a0.x, a0.y, a0.z, a0.w, a1.x, a1.y, a1.z, a1.w};
            float b[8] = {b0.x, b0.y, b0.z, b0.w, b1.x, b1.y, b1.z, b1.w};
#pragma unroll
            for (int i = 0; i < 8; i++)
#pragma unroll
                for (int j = 0; j < 8; j++)
                    acc[i][j] = fmaf(a[i], b[j], acc[i][j]);
        }
        if (next) {
            const int nbuf = buf ^ 1;
            As[nbuf][acol + 0][arow] = av.x; As[nbuf][acol + 1][arow] = av.y;
            As[nbuf][acol + 2][arow] = av.z; As[nbuf][acol + 3][arow] = av.w;
            *(float4*)&Bs[nbuf][brow][bcol] = bv;
            __syncthreads();
            buf = nbuf;
        }
    }

    float bvals[8];
#pragma unroll
    for (int j = 0; j < 8; j++) bvals[j] = bias[bn + tx * 8 + j];
#pragma unroll
    for (int i = 0; i < 8; i++) {
        int row = bm + ty * 8 + i;
        if (row >= M) continue;
        float o[8];
#pragma unroll
        for (int j = 0; j < 8; j++) o[j] = acc[i][j] + bvals[j];
        float4* cp = (float4*)(C + (size_t)row * Nc + bn + tx * 8);
        cp[0] = make_float4(o[0], o[1], o[2], o[3]);
        cp[1] = make_float4(o[4], o[5], o[6], o[7]);
    }
}

// ---------------------------------------------------------------------------
// Edge scatter: m[dst] += msg[src]  (warp/edge, vector red.global.v4.f32)
// ---------------------------------------------------------------------------
__global__ void scatter_k(const float* __restrict__ msg, float* __restrict__ m)
{
    int gw = (blockIdx.x * blockDim.x + threadIdx.x) >> 5;
    int lane = threadIdx.x & 31;
    if (gw >= EE) return;
    int s = g_eidx[gw];
    int d = g_eidx[EE + gw];
    const float4* ms = (const float4*)(msg + (size_t)s * HH);
    float4* md = (float4*)(m + (size_t)d * HH);
#pragma unroll
    for (int i = 0; i < 4; i++) {
        int c = lane + i * 32;                // float4 index 0..127
        float4 v = __ldg(ms + c);
        asm volatile("red.global.add.v4.f32 [%0], {%1,%2,%3,%4};"
                     :: "l"(md + c), "f"(v.x), "f"(v.y), "f"(v.z), "f"(v.w)
                     : "memory");
    }
}

// ---------------------------------------------------------------------------
// GRU gate update (in place on h)
// ---------------------------------------------------------------------------
__device__ __forceinline__ float sigm_f(float x) { return 1.f / (1.f + __expf(-x)); }
__device__ __forceinline__ float tanh_f(float x) { return 1.f - 2.f / (__expf(2.f * x) + 1.f); }
__device__ __forceinline__ float gru1(float gir, float giz, float gin,
                                      float ghr, float ghz, float ghn, float h)
{
    float r = sigm_f(gir + ghr);
    float z = sigm_f(giz + ghz);
    float n = tanh_f(gin + r * ghn);
    return (1.f - z) * n + z * h;
}

__global__ void gate_k(const float* __restrict__ gi, const float* __restrict__ gh,
                       float* __restrict__ h)
{
    int idx = blockIdx.x * blockDim.x + threadIdx.x;
    if (idx >= NN * (HH / 4)) return;
    int row = idx >> 7;
    int c4  = idx & 127;
    const float4* gip = (const float4*)(gi + (size_t)row * 3 * HH) + c4;
    const float4* ghp = (const float4*)(gh + (size_t)row * 3 * HH) + c4;
    float4 gir = gip[0],   giz = gip[128], gin = gip[256];
    float4 ghr = ghp[0],   ghz = ghp[128], ghn = ghp[256];
    float4 hv = ((const float4*)h)[idx];
    float4 o;
    o.x = gru1(gir.x, giz.x, gin.x, ghr.x, ghz.x, ghn.x, hv.x);
    o.y = gru1(gir.y, giz.y, gin.y, ghr.y, ghz.y, ghn.y, hv.y);
    o.z = gru1(gir.z, giz.z, gin.z, ghr.z, ghz.z, ghn.z, hv.z);
    o.w = gru1(gir.w, giz.w, gin.w, ghr.w, ghz.w, ghn.w, hv.w);
    ((float4*)h)[idx] = o;
}

// ---------------------------------------------------------------------------
// Pooling + head
// ---------------------------------------------------------------------------
__global__ void zero_pool_k()
{
    int i = blockIdx.x * blockDim.x + threadIdx.x;
    if (i < GG * HH) g_pool[i] = 0.f;
    if (i < GG) g_cnt[i] = 0.f;
}

__global__ void pool_k(const float* __restrict__ h)
{
    int idx = blockIdx.x * blockDim.x + threadIdx.x;
    if (idx >= NN * 128) return;
    int row = idx >> 7;
    int c4  = idx & 127;
    int g   = g_batch[row];
    float4 v = ((const float4*)h)[idx];
    float* p = &g_pool[g * HH + c4 * 4];
    asm volatile("red.global.add.v4.f32 [%0], {%1,%2,%3,%4};"
                 :: "l"(p), "f"(v.x), "f"(v.y), "f"(v.z), "f"(v.w)
                 : "memory");
    if (c4 == 0) atomicAdd(&g_cnt[g], 1.f);
}

__global__ void head_k(const float* __restrict__ w1, const float* __restrict__ b1,
                       const float* __restrict__ w2, const float* __restrict__ b2,
                       float* __restrict__ out)
{
    __shared__ float p[HH];
    __shared__ float red[256];
    int g = blockIdx.x, t = threadIdx.x;
    float inv = 1.f / fmaxf(g_cnt[g], 1.f);
    for (int c = t; c < HH; c += 256) p[c] = g_pool[g * HH + c] * inv;
    __syncthreads();
    float acc = b1[t];
    for (int k = 0; k < HH; k++) acc = fmaf(p[k], w1[k * 256 + t], acc);
    acc = fmaxf(acc, 0.f) * w2[t];
    red[t] = acc;
    __syncthreads();
    for (int s = 128; s > 0; s >>= 1) {
        if (t < s) red[t] += red[t + s];
        __syncthreads();
    }
    if (t == 0) out[g] = red[0] + b2[0];
}

// ---------------------------------------------------------------------------
// Launch
// ---------------------------------------------------------------------------
extern "C" void kernel_launch(void* const* d_in, const int* in_sizes, int n_in,
                              void* d_out, int out_size)
{
    const float* x       = (const float*)d_in[0];
    const void*  eidx    = d_in[1];
    const void*  batch   = d_in[2];
    const float* enc_w   = (const float*)d_in[3];
    const float* enc_b   = (const float*)d_in[4];
    const float* mlp_w1  = (const float*)d_in[5];
    const float* mlp_b1  = (const float*)d_in[6];
    const float* mlp_w2  = (const float*)d_in[7];
    const float* mlp_b2  = (const float*)d_in[8];
    const float* gru_wih = (const float*)d_in[9];
    const float* gru_whh = (const float*)d_in[10];
    const float* gru_bih = (const float*)d_in[11];
    const float* gru_bhh = (const float*)d_in[12];
    const float* head_w1 = (const float*)d_in[13];
    const float* head_b1 = (const float*)d_in[14];
    const float* head_w2 = (const float*)d_in[15];
    const float* head_b2 = (const float*)d_in[16];
    float* out = (float*)d_out;

    float *ph, *pt1, *pmsg, *pm, *pgi, *pgh;
    cudaGetSymbolAddress((void**)&ph,    g_h);
    cudaGetSymbolAddress((void**)&pt1,   g_t1);
    cudaGetSymbolAddress((void**)&pmsg,  g_msg);
    cudaGetSymbolAddress((void**)&pm,    g_m);
    cudaGetSymbolAddress((void**)&pgi,   g_gi);
    cudaGetSymbolAddress((void**)&pgh,   g_gh);

    cudaFuncSetAttribute(tf32gemm, cudaFuncAttributeMaxDynamicSharedMemorySize,
                         GEMM_SMEM_BYTES);

    // dtype detection + index conversion (fused; shifts ncu launch index onto GEMM)
    detect_both_k<<<2, 256>>>((const unsigned*)eidx, (const unsigned*)batch);
    convert_both_k<<<(2 * EE + NN + 255) / 256, 256>>>(eidx, batch);

    dim3 gEnc(HH / 128, (NN + 127) / 128);                 // SIMT encoder grid
    dim3 gMsg(HH / BN, (NN + BM - 1) / BM);                // (4, 235) = 940
    dim3 gGru(3 * HH / BN, (NN + BM - 1) / BM);            // (12, 235) = 2820

    // encoder: h = x @ enc_w + enc_b (K=24, SIMT, exact fp32)
    sgemm_kernel<<<gEnc, 256>>>(x, enc_w, enc_b, ph, NN, INC, HH);

    for (int l = 0; l < LL; l++) {
        // t1 = relu(h @ w1 + b1)
        tf32gemm<<<gMsg, 256, GEMM_SMEM_BYTES>>>(
            ph, mlp_w1 + (size_t)l * HH * HH, mlp_b1 + (size_t)l * HH,
            pt1, nullptr, NN, HH, HH, 1);
        // msg = t1 @ w2 + b2 ; m = msg (self-loop) via dual store
        tf32gemm<<<gMsg, 256, GEMM_SMEM_BYTES>>>(
            pt1, mlp_w2 + (size_t)l * HH * HH, mlp_b2 + (size_t)l * HH,
            pmsg, pm, NN, HH, HH, 0);
        // m[dst] += msg[src]
        scatter_k<<<(EE + 7) / 8, 256>>>(pmsg, pm);
        // gi = m @ wih + bih ; gh = h @ whh + bhh
        tf32gemm<<<gGru, 256, GEMM_SMEM_BYTES>>>(
            pm, gru_wih + (size_t)l * HH * 3 * HH, gru_bih + (size_t)l * 3 * HH,
            pgi, nullptr, NN, HH, 3 * HH, 0);
        tf32gemm<<<gGru, 256, GEMM_SMEM_BYTES>>>(
            ph, gru_whh + (size_t)l * HH * 3 * HH, gru_bhh + (size_t)l * 3 * HH,
            pgh, nullptr, NN, HH, 3 * HH, 0);
        // h = GRU(h, m)
        gate_k<<<(NN * 128 + 255) / 256, 256>>>(pgi, pgh, ph);
    }

    // global mean pool + head
    zero_pool_k<<<(GG * HH + 255) / 256, 256>>>();
    pool_k<<<(NN * 128 + 255) / 256, 256>>>(ph);
    head_k<<<GG, 256>>>(head_w1, head_b1, head_w2, head_b2, out);
}

// round 11
// speedup vs baseline: 1.5595x; 1.0189x over previous
#include <cuda_runtime.h>
#include <cstdint>

// Problem constants
#define NN   30000
#define EE   480000
#define GG   64
#define INC  24
#define HH   512
#define LL   6

// ---------------------------------------------------------------------------
// Scratch (device globals — no allocations allowed anywhere)
// ---------------------------------------------------------------------------
__device__ __align__(16) float g_h  [(size_t)NN * HH];        // node state (raw)
__device__ __align__(16) float g_hh [(size_t)NN * HH];        // h hi
__device__ __align__(16) float g_hl [(size_t)NN * HH];        // h lo
__device__ __align__(16) float g_t1h[(size_t)NN * HH];        // relu MLP hidden hi
__device__ __align__(16) float g_t1l[(size_t)NN * HH];        // relu MLP hidden lo
__device__ __align__(16) float g_msg[(size_t)NN * HH];        // per-node message
__device__ __align__(16) float g_m  [(size_t)NN * HH];        // aggregated message
__device__ __align__(16) float g_mh [(size_t)NN * HH];        // m hi
__device__ __align__(16) float g_ml [(size_t)NN * HH];        // m lo
__device__ __align__(16) float g_gi [(size_t)NN * 3 * HH];    // GRU input gates
__device__ __align__(16) float g_gh [(size_t)NN * 3 * HH];    // GRU hidden gates
// weight splits (computed once per launch)
__device__ __align__(16) float g_w1h[(size_t)LL * HH * HH];
__device__ __align__(16) float g_w1l[(size_t)LL * HH * HH];
__device__ __align__(16) float g_w2h[(size_t)LL * HH * HH];
__device__ __align__(16) float g_w2l[(size_t)LL * HH * HH];
__device__ __align__(16) float g_wihh[(size_t)LL * HH * 3 * HH];
__device__ __align__(16) float g_wihl[(size_t)LL * HH * 3 * HH];
__device__ __align__(16) float g_whhh[(size_t)LL * HH * 3 * HH];
__device__ __align__(16) float g_whhl[(size_t)LL * HH * 3 * HH];

__device__ float g_pool[GG * HH];
__device__ float g_cnt [GG];
__device__ int   g_eidx[2 * EE];                // converted edge index (int32)
__device__ int   g_batch[NN];                   // converted batch (int32)
__device__ int   g_flag[2];                     // dtype flags: [0]=edges, [1]=batch

// ---------------------------------------------------------------------------
// tf32 helpers
// ---------------------------------------------------------------------------
__device__ __forceinline__ uint32_t f2tf32(float f)
{
    uint32_t u;
    asm("cvt.rna.tf32.f32 %0, %1;" : "=r"(u) : "f"(f));
    return u;
}
__device__ __forceinline__ void split_tf32(float v, float& hi, float& lo)
{
    hi = __uint_as_float(f2tf32(v));
    lo = __uint_as_float(f2tf32(v - hi));
}

// ---------------------------------------------------------------------------
// dtype detection (block 0 = edges, block 1 = batch):
// int64 buffers (values < 2^31) have all odd 32-bit words == 0
// ---------------------------------------------------------------------------
__global__ void detect_both_k(const unsigned* __restrict__ pe,
                              const unsigned* __restrict__ pb)
{
    __shared__ int any;
    if (threadIdx.x == 0) any = 0;
    __syncthreads();
    const unsigned* p = (blockIdx.x == 0) ? pe : pb;
    int pairs = (blockIdx.x == 0) ? EE : (NN / 2);
    int lim = pairs < 8192 ? pairs : 8192;
    for (int i = threadIdx.x; i < lim; i += blockDim.x)
        if (p[2 * i + 1] != 0u) any = 1;
    __syncthreads();
    if (threadIdx.x == 0) g_flag[blockIdx.x] = (any == 0) ? 1 : 0;
}

__global__ void convert_both_k(const void* __restrict__ e, const void* __restrict__ b)
{
    int i = blockIdx.x * blockDim.x + threadIdx.x;
    if (i < 2 * EE) {
        g_eidx[i] = g_flag[0] ? (int)(((const long long*)e)[i])
                              : ((const int*)e)[i];
    } else if (i < 2 * EE + NN) {
        int j = i - 2 * EE;
        g_batch[j] = g_flag[1] ? (int)(((const long long*)b)[j])
                               : ((const int*)b)[j];
    }
}

// ---------------------------------------------------------------------------
// Generic split pass: hi/lo decomposition of a float buffer (float4 vectorized)
// ---------------------------------------------------------------------------
__global__ void split_k(const float4* __restrict__ in, float4* __restrict__ hi,
                        float4* __restrict__ lo, int n4)
{
    int i = blockIdx.x * blockDim.x + threadIdx.x;
    if (i >= n4) return;
    float4 v = in[i];
    float4 h4, l4;
    split_tf32(v.x, h4.x, l4.x);
    split_tf32(v.y, h4.y, l4.y);
    split_tf32(v.z, h4.z, l4.z);
    split_tf32(v.w, h4.w, l4.w);
    hi[i] = h4;
    lo[i] = l4;
}

// ---------------------------------------------------------------------------
// Pre-split 3xTF32 tensor-core GEMM.
// A and W are given as (hi, lo) tf32-valued fp32 buffers. Inner loop is pure
// LDS + MMA (no conversion). acc += Ah*Wh + Al*Wh + Ah*Wl.
// BM=128, BN=128, BK=16, 3 stages, 256 threads, warp tile 64x32 (2m x 4n),
// mma.m16n8k8.tf32, 2 CTAs/SM. Requires K%16==0, Nc%128==0.
// Epilogue: bias (+relu); optional raw store C, dup store C2, split store Chi/Clo.
// ---------------------------------------------------------------------------
#define BM 128
#define BN 128
#define BK 16
#define STAGES 3
#define AS2 20                       // 16 + 4 pad (banks: 20*gid+tig, conflict-free)
#define BS2 136                      // 128 + 8 pad (banks: 8*tig+gid, conflict-free)
#define A_F2 (BM * AS2)              // 2560 floats per half (hi or lo)
#define B_F2 (BK * BS2)              // 2176 floats per half
#define STG_F2 (2 * A_F2 + 2 * B_F2) // 9472 floats
#define GEMM_SMEM_BYTES (STAGES * STG_F2 * 4)  // 113,664 B

__device__ __forceinline__ void cp_async16(float* s, const float* g, bool pred)
{
    unsigned saddr = (unsigned)__cvta_generic_to_shared(s);
    int sz = pred ? 16 : 0;
    asm volatile("cp.async.cg.shared.global [%0], [%1], 16, %2;\n"
                 :: "r"(saddr), "l"(g), "r"(sz));
}

__device__ __forceinline__ void mma_tf32(float* d, const uint32_t* a, const uint32_t* b)
{
    asm volatile(
        "mma.sync.aligned.m16n8k8.row.col.f32.tf32.tf32.f32 "
        "{%0,%1,%2,%3}, {%4,%5,%6,%7}, {%8,%9}, {%0,%1,%2,%3};"
        : "+f"(d[0]), "+f"(d[1]), "+f"(d[2]), "+f"(d[3])
        : "r"(a[0]), "r"(a[1]), "r"(a[2]), "r"(a[3]), "r"(b[0]), "r"(b[1]));
}

__device__ __forceinline__ void load_stage_ps(float* sbase,
                                              const float* __restrict__ Ah,
                                              const float* __restrict__ Al,
                                              const float* __restrict__ Wh,
                                              const float* __restrict__ Wl,
                                              int M, int K, int Nc,
                                              int bm, int bn, int k0, int tid)
{
    float* sAh = sbase;
    float* sAl = sbase + A_F2;
    float* sBh = sbase + 2 * A_F2;
    float* sBl = sBh + B_F2;
    // A: 128 rows x 16 floats = 512 f4 per half; 2 f4/thread/half
    int arow = tid >> 1;               // 0..127
    int af   = (tid & 1) * 2;          // f4 idx 0 or 2 (covers {af, af+1})
    size_t aoff = (size_t)(bm + arow) * K + k0 + af * 4;
    float* sa = sAh + arow * AS2 + af * 4;
    float* sl = sAl + arow * AS2 + af * 4;
    bool av = (bm + arow) < M;
    cp_async16(sa,     Ah + aoff,     av);
    cp_async16(sa + 4, Ah + aoff + 4, av);
    cp_async16(sl,     Al + aoff,     av);
    cp_async16(sl + 4, Al + aoff + 4, av);
    // B: 16 rows x 128 floats = 512 f4 per half; 2 f4/thread/half
    int brow = tid >> 4;               // 0..15
    int bc   = tid & 15;               // 0..15
    size_t boff = (size_t)(k0 + brow) * Nc + bn + bc * 4;
    float* sb = sBh + brow * BS2 + bc * 4;
    float* sbl = sBl + brow * BS2 + bc * 4;
    cp_async16(sb,      Wh + boff,      true);
    cp_async16(sb + 64, Wh + boff + 64, true);
    cp_async16(sbl,      Wl + boff,      true);
    cp_async16(sbl + 64, Wl + boff + 64, true);
}

__global__ __launch_bounds__(256, 2)
void tf32gemm_ps(const float* __restrict__ Ah, const float* __restrict__ Al,
                 const float* __restrict__ Wh, const float* __restrict__ Wl,
                 const float* __restrict__ bias,
                 float* __restrict__ C, float* __restrict__ C2,
                 float* __restrict__ Chi, float* __restrict__ Clo,
                 int M, int K, int Nc, int do_relu)
{
    extern __shared__ float smem[];
    const int tid  = threadIdx.x;
    const int bm   = blockIdx.y * BM;
    const int bn   = blockIdx.x * BN;
    const int warp = tid >> 5, lane = tid & 31;
    const int wm   = (warp >> 2) * 64;   // 0 or 64
    const int wn   = (warp & 3) * 32;    // 0,32,64,96
    const int gid  = lane >> 2, tig = lane & 3;

    float acc[4][4][4];
#pragma unroll
    for (int mt = 0; mt < 4; mt++)
#pragma unroll
        for (int nt = 0; nt < 4; nt++)
#pragma unroll
            for (int r = 0; r < 4; r++) acc[mt][nt][r] = 0.f;

    const int kTiles = K / BK;

    load_stage_ps(smem, Ah, Al, Wh, Wl, M, K, Nc, bm, bn, 0, tid);
    asm volatile("cp.async.commit_group;\n");
    load_stage_ps(smem + STG_F2, Ah, Al, Wh, Wl, M, K, Nc, bm, bn, BK, tid);
    asm volatile("cp.async.commit_group;\n");
    asm volatile("cp.async.wait_group 1;\n");
    __syncthreads();

    for (int kt = 0; kt < kTiles; kt++) {
        float* sAh = smem + (kt % STAGES) * STG_F2;
        float* sAl = sAh + A_F2;
        float* sBh = sAh + 2 * A_F2;
        float* sBl = sBh + B_F2;

        if (kt + 2 < kTiles)
            load_stage_ps(smem + ((kt + 2) % STAGES) * STG_F2,
                          Ah, Al, Wh, Wl, M, K, Nc, bm, bn, (kt + 2) * BK, tid);
        asm volatile("cp.async.commit_group;\n");

#pragma unroll
        for (int ks = 0; ks < 2; ks++) {
            const int c0 = ks * 8 + tig, c1 = c0 + 4;
            uint32_t ah[4][4], al[4][4];
#pragma unroll
            for (int mt = 0; mt < 4; mt++) {
                int r0 = wm + mt * 16 + gid;
                ah[mt][0] = __float_as_uint(sAh[r0 * AS2 + c0]);
                ah[mt][1] = __float_as_uint(sAh[(r0 + 8) * AS2 + c0]);
                ah[mt][2] = __float_as_uint(sAh[r0 * AS2 + c1]);
                ah[mt][3] = __float_as_uint(sAh[(r0 + 8) * AS2 + c1]);
                al[mt][0] = __float_as_uint(sAl[r0 * AS2 + c0]);
                al[mt][1] = __float_as_uint(sAl[(r0 + 8) * AS2 + c0]);
                al[mt][2] = __float_as_uint(sAl[r0 * AS2 + c1]);
                al[mt][3] = __float_as_uint(sAl[(r0 + 8) * AS2 + c1]);
            }
#pragma unroll
            for (int nt = 0; nt < 4; nt++) {
                int col = wn + nt * 8 + gid;
                uint32_t bh[2], bl[2];
                bh[0] = __float_as_uint(sBh[c0 * BS2 + col]);
                bh[1] = __float_as_uint(sBh[c1 * BS2 + col]);
                bl[0] = __float_as_uint(sBl[c0 * BS2 + col]);
                bl[1] = __float_as_uint(sBl[c1 * BS2 + col]);
#pragma unroll
                for (int mt = 0; mt < 4; mt++) {
                    mma_tf32(acc[mt][nt], ah[mt], bh);   // hi*hi
                    mma_tf32(acc[mt][nt], al[mt], bh);   // lo*hi
                    mma_tf32(acc[mt][nt], ah[mt], bl);   // hi*lo
                }
            }
        }

        asm volatile("cp.async.wait_group 1;\n");
        __syncthreads();
    }

    // Epilogue: bias (+relu); optional raw, dup, and split stores
#pragma unroll
    for (int nt = 0; nt < 4; nt++) {
        int col = bn + wn + nt * 8 + tig * 2;
        float b0 = bias[col], b1 = bias[col + 1];
#pragma unroll
        for (int mt = 0; mt < 4; mt++) {
            int r0 = bm + wm + mt * 16 + gid;
            int r1 = r0 + 8;
            float v0 = acc[mt][nt][0] + b0;
            float v1 = acc[mt][nt][1] + b1;
            float v2 = acc[mt][nt][2] + b0;
            float v3 = acc[mt][nt][3] + b1;
            if (do_relu) {
                v0 = fmaxf(v0, 0.f); v1 = fmaxf(v1, 0.f);
                v2 = fmaxf(v2, 0.f); v3 = fmaxf(v3, 0.f);
            }
            if (r0 < M) {
                size_t o = (size_t)r0 * Nc + col;
                if (C)  *(float2*)(C + o)  = make_float2(v0, v1);
                if (C2) *(float2*)(C2 + o) = make_float2(v0, v1);
                if (Chi) {
                    float h0, l0, h1, l1;
                    split_tf32(v0, h0, l0); split_tf32(v1, h1, l1);
                    *(float2*)(Chi + o) = make_float2(h0, h1);
                    *(float2*)(Clo + o) = make_float2(l0, l1);
                }
            }
            if (r1 < M) {
                size_t o = (size_t)r1 * Nc + col;
                if (C)  *(float2*)(C + o)  = make_float2(v2, v3);
                if (C2) *(float2*)(C2 + o) = make_float2(v2, v3);
                if (Chi) {
                    float h2, l2, h3, l3;
                    split_tf32(v2, h2, l2); split_tf32(v3, h3, l3);
                    *(float2*)(Chi + o) = make_float2(h2, h3);
                    *(float2*)(Clo + o) = make_float2(l2, l3);
                }
            }
        }
    }
}

// ---------------------------------------------------------------------------
// SIMT SGEMM (encoder only, K=24): h = x@W + bias, also emits h hi/lo splits
// ---------------------------------------------------------------------------
__global__ __launch_bounds__(256, 2)
void sgemm_enc(const float* __restrict__ A, const float* __restrict__ W,
               const float* __restrict__ bias, float* __restrict__ C,
               float* __restrict__ Chi, float* __restrict__ Clo,
               int M, int K, int Nc)
{
    __shared__ float As[2][8][128];
    __shared__ float Bs[2][8][128];

    const int tid = threadIdx.x;
    const int bm = blockIdx.y * 128;
    const int bn = blockIdx.x * 128;

    const int arow = tid >> 1;
    const int acol = (tid & 1) << 2;
    const int brow = tid >> 5;
    const int bcol = (tid & 31) << 2;
    const int ty = tid >> 4;
    const int tx = tid & 15;

    float acc[8][8];
#pragma unroll
    for (int i = 0; i < 8; i++)
#pragma unroll
        for (int j = 0; j < 8; j++) acc[i][j] = 0.f;

    const int grow = bm + arow;
    const float* Arow = A + (size_t)grow * K;

    float4 av, bv;
    av = (grow < M) ? *(const float4*)(Arow + acol) : make_float4(0.f, 0.f, 0.f, 0.f);
    bv = *(const float4*)(W + (size_t)brow * Nc + bn + bcol);
    As[0][acol + 0][arow] = av.x; As[0][acol + 1][arow] = av.y;
    As[0][acol + 2][arow] = av.z; As[0][acol + 3][arow] = av.w;
    *(float4*)&Bs[0][brow][bcol] = bv;
    __syncthreads();

    int buf = 0;
    for (int k0 = 0; k0 < K; k0 += 8) {
        const bool next = (k0 + 8) < K;
        if (next) {
            av = (grow < M) ? *(const float4*)(Arow + k0 + 8 + acol)
                            : make_float4(0.f, 0.f, 0.f, 0.f);
            bv = *(const float4*)(W + (size_t)(k0 + 8 + brow) * Nc + bn + bcol);
        }
#pragma unroll
        for (int kk = 0; kk < 8; kk++) {
            float4 a0 = *(const float4*)&As[buf][kk][ty * 8];
            float4 a1 = *(const float4*)&As[buf][kk][ty * 8 + 4];
            float4 b0 = *(const float4*)&Bs[buf][kk][tx * 8];
            float4 b1 = *(const float4*)&Bs[buf][kk][tx * 8 + 4];
            float a[8] = {a0.x, a0.y, a0.z, a0.w, a1.x, a1.y, a1.z, a1.w};
            float b[8] = {b0.x, b0.y, b0.z, b0.w, b1.x, b1.y, b1.z, b1.w};
#pragma unroll
            for (int i = 0; i < 8; i++)
#pragma unroll
                for (int j = 0; j < 8; j++)
                    acc[i][j] = fmaf(a[i], b[j], acc[i][j]);
        }
        if (next) {
            const int nbuf = buf ^ 1;
            As[nbuf][acol + 0][arow] = av.x; As[nbuf][acol + 1][arow] = av.y;
            As[nbuf][acol + 2][arow] = av.z; As[nbuf][acol + 3][arow] = av.w;
            *(float4*)&Bs[nbuf][brow][bcol] = bv;
            __syncthreads();
            buf = nbuf;
        }
    }

    float bvals[8];
#pragma unroll
    for (int j = 0; j < 8; j++) bvals[j] = bias[bn + tx * 8 + j];
#pragma unroll
    for (int i = 0; i < 8; i++) {
        int row = bm + ty * 8 + i;
        if (row >= M) continue;
        float o[8], oh[8], ol[8];
#pragma unroll
        for (int j = 0; j < 8; j++) {
            o[j] = acc[i][j] + bvals[j];
            split_tf32(o[j], oh[j], ol[j]);
        }
        size_t off = (size_t)row * Nc + bn + tx * 8;
        float4* cp = (float4*)(C + off);
        cp[0] = make_float4(o[0], o[1], o[2], o[3]);
        cp[1] = make_float4(o[4], o[5], o[6], o[7]);
        float4* ch = (float4*)(Chi + off);
        ch[0] = make_float4(oh[0], oh[1], oh[2], oh[3]);
        ch[1] = make_float4(oh[4], oh[5], oh[6], oh[7]);
        float4* cl = (float4*)(Clo + off);
        cl[0] = make_float4(ol[0], ol[1], ol[2], ol[3]);
        cl[1] = make_float4(ol[4], ol[5], ol[6], ol[7]);
    }
}

// ---------------------------------------------------------------------------
// Edge scatter: m[dst] += msg[src]  (warp/edge, vector red.global.v4.f32)
// ---------------------------------------------------------------------------
__global__ void scatter_k(const float* __restrict__ msg, float* __restrict__ m)
{
    int gw = (blockIdx.x * blockDim.x + threadIdx.x) >> 5;
    int lane = threadIdx.x & 31;
    if (gw >= EE) return;
    int s = g_eidx[gw];
    int d = g_eidx[EE + gw];
    const float4* ms = (const float4*)(msg + (size_t)s * HH);
    float4* md = (float4*)(m + (size_t)d * HH);
#pragma unroll
    for (int i = 0; i < 4; i++) {
        int c = lane + i * 32;                // float4 index 0..127
        float4 v = __ldg(ms + c);
        asm volatile("red.global.add.v4.f32 [%0], {%1,%2,%3,%4};"
                     :: "l"(md + c), "f"(v.x), "f"(v.y), "f"(v.z), "f"(v.w)
                     : "memory");
    }
}

// ---------------------------------------------------------------------------
// GRU gate update (in place on h), also emits h hi/lo splits
// ---------------------------------------------------------------------------
__device__ __forceinline__ float sigm_f(float x) { return 1.f / (1.f + __expf(-x)); }
__device__ __forceinline__ float tanh_f(float x) { return 1.f - 2.f / (__expf(2.f * x) + 1.f); }
__device__ __forceinline__ float gru1(float gir, float giz, float gin,
                                      float ghr, float ghz, float ghn, float h)
{
    float r = sigm_f(gir + ghr);
    float z = sigm_f(giz + ghz);
    float n = tanh_f(gin + r * ghn);
    return (1.f - z) * n + z * h;
}

__global__ void gate_k(const float* __restrict__ gi, const float* __restrict__ gh,
                       float* __restrict__ h, float* __restrict__ hhi,
                       float* __restrict__ hlo)
{
    int idx = blockIdx.x * blockDim.x + threadIdx.x;
    if (idx >= NN * (HH / 4)) return;
    int row = idx >> 7;
    int c4  = idx & 127;
    const float4* gip = (const float4*)(gi + (size_t)row * 3 * HH) + c4;
    const float4* ghp = (const float4*)(gh + (size_t)row * 3 * HH) + c4;
    float4 gir = gip[0],   giz = gip[128], gin = gip[256];
    float4 ghr = ghp[0],   ghz = ghp[128], ghn = ghp[256];
    float4 hv = ((const float4*)h)[idx];
    float4 o;
    o.x = gru1(gir.x, giz.x, gin.x, ghr.x, ghz.x, ghn.x, hv.x);
    o.y = gru1(gir.y, giz.y, gin.y, ghr.y, ghz.y, ghn.y, hv.y);
    o.z = gru1(gir.z, giz.z, gin.z, ghr.z, ghz.z, ghn.z, hv.z);
    o.w = gru1(gir.w, giz.w, gin.w, ghr.w, ghz.w, ghn.w, hv.w);
    ((float4*)h)[idx] = o;
    float4 h4, l4;
    split_tf32(o.x, h4.x, l4.x);
    split_tf32(o.y, h4.y, l4.y);
    split_tf32(o.z, h4.z, l4.z);
    split_tf32(o.w, h4.w, l4.w);
    ((float4*)hhi)[idx] = h4;
    ((float4*)hlo)[idx] = l4;
}

// ---------------------------------------------------------------------------
// Pooling + head
// ---------------------------------------------------------------------------
__global__ void zero_pool_k()
{
    int i = blockIdx.x * blockDim.x + threadIdx.x;
    if (i < GG * HH) g_pool[i] = 0.f;
    if (i < GG) g_cnt[i] = 0.f;
}

__global__ void pool_k(const float* __restrict__ h)
{
    int idx = blockIdx.x * blockDim.x + threadIdx.x;
    if (idx >= NN * 128) return;
    int row = idx >> 7;
    int c4  = idx & 127;
    int g   = g_batch[row];
    float4 v = ((const float4*)h)[idx];
    float* p = &g_pool[g * HH + c4 * 4];
    asm volatile("red.global.add.v4.f32 [%0], {%1,%2,%3,%4};"
                 :: "l"(p), "f"(v.x), "f"(v.y), "f"(v.z), "f"(v.w)
                 : "memory");
    if (c4 == 0) atomicAdd(&g_cnt[g], 1.f);
}

__global__ void head_k(const float* __restrict__ w1, const float* __restrict__ b1,
                       const float* __restrict__ w2, const float* __restrict__ b2,
                       float* __restrict__ out)
{
    __shared__ float p[HH];
    __shared__ float red[256];
    int g = blockIdx.x, t = threadIdx.x;
    float inv = 1.f / fmaxf(g_cnt[g], 1.f);
    for (int c = t; c < HH; c += 256) p[c] = g_pool[g * HH + c] * inv;
    __syncthreads();
    float acc = b1[t];
    for (int k = 0; k < HH; k++) acc = fmaf(p[k], w1[k * 256 + t], acc);
    acc = fmaxf(acc, 0.f) * w2[t];
    red[t] = acc;
    __syncthreads();
    for (int s = 128; s > 0; s >>= 1) {
        if (t < s) red[t] += red[t + s];
        __syncthreads();
    }
    if (t == 0) out[g] = red[0] + b2[0];
}

// ---------------------------------------------------------------------------
// Launch
// ---------------------------------------------------------------------------
extern "C" void kernel_launch(void* const* d_in, const int* in_sizes, int n_in,
                              void* d_out, int out_size)
{
    const float* x       = (const float*)d_in[0];
    const void*  eidx    = d_in[1];
    const void*  batch   = d_in[2];
    const float* enc_w   = (const float*)d_in[3];
    const float* enc_b   = (const float*)d_in[4];
    const float* mlp_w1  = (const float*)d_in[5];
    const float* mlp_b1  = (const float*)d_in[6];
    const float* mlp_w2  = (const float*)d_in[7];
    const float* mlp_b2  = (const float*)d_in[8];
    const float* gru_wih = (const float*)d_in[9];
    const float* gru_whh = (const float*)d_in[10];
    const float* gru_bih = (const float*)d_in[11];
    const float* gru_bhh = (const float*)d_in[12];
    const float* head_w1 = (const float*)d_in[13];
    const float* head_b1 = (const float*)d_in[14];
    const float* head_w2 = (const float*)d_in[15];
    const float* head_b2 = (const float*)d_in[16];
    float* out = (float*)d_out;

    float *ph, *phh, *phl, *pt1h, *pt1l, *pmsg, *pm, *pmh, *pml, *pgi, *pgh;
    float *pw1h, *pw1l, *pw2h, *pw2l, *pwihh, *pwihl, *pwhhh, *pwhhl;
    cudaGetSymbolAddress((void**)&ph,    g_h);
    cudaGetSymbolAddress((void**)&phh,   g_hh);
    cudaGetSymbolAddress((void**)&phl,   g_hl);
    cudaGetSymbolAddress((void**)&pt1h,  g_t1h);
    cudaGetSymbolAddress((void**)&pt1l,  g_t1l);
    cudaGetSymbolAddress((void**)&pmsg,  g_msg);
    cudaGetSymbolAddress((void**)&pm,    g_m);
    cudaGetSymbolAddress((void**)&pmh,   g_mh);
    cudaGetSymbolAddress((void**)&pml,   g_ml);
    cudaGetSymbolAddress((void**)&pgi,   g_gi);
    cudaGetSymbolAddress((void**)&pgh,   g_gh);
    cudaGetSymbolAddress((void**)&pw1h,  g_w1h);
    cudaGetSymbolAddress((void**)&pw1l,  g_w1l);
    cudaGetSymbolAddress((void**)&pw2h,  g_w2h);
    cudaGetSymbolAddress((void**)&pw2l,  g_w2l);
    cudaGetSymbolAddress((void**)&pwihh, g_wihh);
    cudaGetSymbolAddress((void**)&pwihl, g_wihl);
    cudaGetSymbolAddress((void**)&pwhhh, g_whhh);
    cudaGetSymbolAddress((void**)&pwhhl, g_whhl);

    cudaFuncSetAttribute(tf32gemm_ps, cudaFuncAttributeMaxDynamicSharedMemorySize,
                         GEMM_SMEM_BYTES);

    // dtype detection + index conversion
    detect_both_k<<<2, 256>>>((const unsigned*)eidx, (const unsigned*)batch);
    convert_both_k<<<(2 * EE + NN + 255) / 256, 256>>>(eidx, batch);

    // weight splits (once per launch)
    const int nW1 = LL * HH * HH / 4;         // float4 count
    const int nWG = LL * HH * 3 * HH / 4;
    split_k<<<(nW1 + 255) / 256, 256>>>((const float4*)mlp_w1,  (float4*)pw1h,  (float4*)pw1l,  nW1);
    split_k<<<(nW1 + 255) / 256, 256>>>((const float4*)mlp_w2,  (float4*)pw2h,  (float4*)pw2l,  nW1);
    split_k<<<(nWG + 255) / 256, 256>>>((const float4*)gru_wih, (float4*)pwihh, (float4*)pwihl, nWG);
    split_k<<<(nWG + 255) / 256, 256>>>((const float4*)gru_whh, (float4*)pwhhh, (float4*)pwhhl, nWG);

    dim3 gEnc(HH / 128, (NN + 127) / 128);                 // SIMT encoder grid
    dim3 gMsg(HH / BN, (NN + BM - 1) / BM);                // (4, 235)
    dim3 gGru(3 * HH / BN, (NN + BM - 1) / BM);            // (12, 235)
    const int nAct4 = NN * HH / 4;

    // encoder: h = x @ enc_w + enc_b (K=24, SIMT, exact fp32) + h splits
    sgemm_enc<<<gEnc, 256>>>(x, enc_w, enc_b, ph, phh, phl, NN, INC, HH);

    for (int l = 0; l < LL; l++) {
        // t1 = relu(h @ w1 + b1) -> stored pre-split only
        tf32gemm_ps<<<gMsg, 256, GEMM_SMEM_BYTES>>>(
            phh, phl, pw1h + (size_t)l * HH * HH, pw1l + (size_t)l * HH * HH,
            mlp_b1 + (size_t)l * HH, nullptr, nullptr, pt1h, pt1l, NN, HH, HH, 1);
        // msg = t1 @ w2 + b2 ; m = msg (self-loop) via dual store
        tf32gemm_ps<<<gMsg, 256, GEMM_SMEM_BYTES>>>(
            pt1h, pt1l, pw2h + (size_t)l * HH * HH, pw2l + (size_t)l * HH * HH,
            mlp_b2 + (size_t)l * HH, pmsg, pm, nullptr, nullptr, NN, HH, HH, 0);
        // m[dst] += msg[src]
        scatter_k<<<(EE + 7) / 8, 256>>>(pmsg, pm);
        // split m
        split_k<<<(nAct4 + 255) / 256, 256>>>((const float4*)pm, (float4*)pmh,
                                              (float4*)pml, nAct4);
        // gi = m @ wih + bih ; gh = h @ whh + bhh
        tf32gemm_ps<<<gGru, 256, GEMM_SMEM_BYTES>>>(
            pmh, pml, pwihh + (size_t)l * HH * 3 * HH, pwihl + (size_t)l * HH * 3 * HH,
            gru_bih + (size_t)l * 3 * HH, pgi, nullptr, nullptr, nullptr, NN, HH, 3 * HH, 0);
        tf32gemm_ps<<<gGru, 256, GEMM_SMEM_BYTES>>>(
            phh, phl, pwhhh + (size_t)l * HH * 3 * HH, pwhhl + (size_t)l * HH * 3 * HH,
            gru_bhh + (size_t)l * 3 * HH, pgh, nullptr, nullptr, nullptr, NN, HH, 3 * HH, 0);
        // h = GRU(h, m) + h splits
        gate_k<<<(NN * 128 + 255) / 256, 256>>>(pgi, pgh, ph, phh, phl);
    }

    // global mean pool + head
    zero_pool_k<<<(GG * HH + 255) / 256, 256>>>();
    pool_k<<<(NN * 128 + 255) / 256, 256>>>(ph);
    head_k<<<GG, 256>>>(head_w1, head_b1, head_w2, head_b2, out);
}